// round 1
// baseline (speedup 1.0000x reference)
#include <cuda_runtime.h>
#include <cuda_bf16.h>
#include <math.h>

// ---------------------------------------------------------------------------
// Problem constants
// ---------------------------------------------------------------------------
static constexpr int Bb   = 4;
static constexpr int Nn   = 2304;      // 48*48
static constexpr int Cc   = 256;
static constexpr int NH   = 8;
static constexpr int HD   = 32;
static constexpr int HS   = 48;
static constexpr int HID  = 4 * Cc;    // 1024
static constexpr int ROWS = Bb * Nn;   // 9216
static constexpr float SCALE = 0.17677669529663687f; // 32^-0.5

// Neighbor offsets with dy*dy+dx*dx <= 9  (29 of them)
__constant__ int c_dy[29] = {-3,-2,-2,-2,-2,-2,-1,-1,-1,-1,-1, 0,0,0,0,0,0,0, 1,1,1,1,1, 2,2,2,2,2, 3};
__constant__ int c_dx[29] = { 0,-2,-1, 0, 1, 2,-2,-1, 0, 1, 2,-3,-2,-1,0,1,2,3,-2,-1,0,1,2,-2,-1,0,1,2, 0};

// ---------------------------------------------------------------------------
// Scratch (no cudaMalloc allowed)
// ---------------------------------------------------------------------------
__device__ float g_h   [ROWS * Cc];
__device__ float g_hkv [ROWS * Cc];
__device__ float g_q   [ROWS * Cc];
__device__ float g_k   [ROWS * Cc];
__device__ float g_v   [ROWS * Cc];
__device__ float g_att [ROWS * Cc];
__device__ float g_x2  [ROWS * Cc];
__device__ float g_m   [ROWS * Cc];
__device__ float g_t   [ROWS * HID];

// ---------------------------------------------------------------------------
// LayerNorm: one warp per row of 256
// ---------------------------------------------------------------------------
__global__ void ln_kernel(const float* __restrict__ x,
                          const float* __restrict__ g,
                          const float* __restrict__ b,
                          float* __restrict__ o, int rows)
{
    int gw   = (blockIdx.x * blockDim.x + threadIdx.x) >> 5;
    int lane = threadIdx.x & 31;
    if (gw >= rows) return;
    const float* xr = x + (size_t)gw * Cc;
    float f[8], s = 0.f, ss = 0.f;
#pragma unroll
    for (int i = 0; i < 8; i++) {
        f[i] = xr[lane + 32 * i];
        s  += f[i];
        ss += f[i] * f[i];
    }
#pragma unroll
    for (int off = 16; off; off >>= 1) {
        s  += __shfl_xor_sync(0xffffffffu, s,  off);
        ss += __shfl_xor_sync(0xffffffffu, ss, off);
    }
    float mu  = s * (1.f / 256.f);
    float var = ss * (1.f / 256.f) - mu * mu;
    float inv = rsqrtf(var + 1e-6f);
    float* orow = o + (size_t)gw * Cc;
#pragma unroll
    for (int i = 0; i < 8; i++) {
        int c = lane + 32 * i;
        orow[c] = (f[i] - mu) * inv * g[c] + b[c];
    }
}

// ---------------------------------------------------------------------------
// SGEMM: C[M,N] = A[M,K] @ W[K,N] + bias  (+res / gelu epilogues)
// BM=128, BN=64, BK=16, 256 threads, 8x4 per thread.
// M % 128 == 0, N % 64 == 0, K % 16 == 0 guaranteed by problem shapes.
// EPI: 0 = none, 1 = +res, 2 = gelu(exact)
// ---------------------------------------------------------------------------
template <int EPI>
__global__ void sgemm(const float* __restrict__ A,
                      const float* __restrict__ W,
                      const float* __restrict__ bias,
                      const float* __restrict__ res,
                      float* __restrict__ C,
                      int M, int N, int K)
{
    constexpr int BM = 128, BN = 64, BK = 16;
    __shared__ float As[BM][BK + 1];
    __shared__ float Bs[BK][BN];

    int tid = threadIdx.x;
    int bm = blockIdx.y, bn = blockIdx.x;
    int ty = tid >> 4, tx = tid & 15;

    float acc[8][4] = {};
    const float* Ab = A + (size_t)bm * BM * K;
    const float* Wb = W + (size_t)bn * BN;

    for (int k0 = 0; k0 < K; k0 += BK) {
        // load A tile 128x16 (512 float4, slot = s*256 + tid for coalescing)
#pragma unroll
        for (int s = 0; s < 2; s++) {
            int slot = s * 256 + tid;
            int r = slot >> 2, c4 = slot & 3;
            float4 va = *(const float4*)(Ab + (size_t)r * K + k0 + c4 * 4);
            As[r][c4 * 4 + 0] = va.x;
            As[r][c4 * 4 + 1] = va.y;
            As[r][c4 * 4 + 2] = va.z;
            As[r][c4 * 4 + 3] = va.w;
        }
        // load B tile 16x64 (256 float4, 1 per thread)
        {
            int r = tid >> 4, c4 = tid & 15;
            float4 vb = *(const float4*)(Wb + (size_t)(k0 + r) * N + c4 * 4);
            *(float4*)&Bs[r][c4 * 4] = vb;
        }
        __syncthreads();
#pragma unroll
        for (int k = 0; k < BK; k++) {
            float a[8], bb[4];
#pragma unroll
            for (int i = 0; i < 8; i++) a[i] = As[ty * 8 + i][k];
#pragma unroll
            for (int j = 0; j < 4; j++) bb[j] = Bs[k][tx * 4 + j];
#pragma unroll
            for (int i = 0; i < 8; i++)
#pragma unroll
                for (int j = 0; j < 4; j++)
                    acc[i][j] += a[i] * bb[j];
        }
        __syncthreads();
    }

#pragma unroll
    for (int i = 0; i < 8; i++) {
        int r = bm * BM + ty * 8 + i;
#pragma unroll
        for (int j = 0; j < 4; j++) {
            int c = bn * BN + tx * 4 + j;
            float vv = acc[i][j] + bias[c];
            if (EPI == 1) vv += res[(size_t)r * N + c];
            if (EPI == 2) vv = 0.5f * vv * (1.f + erff(vv * 0.70710678118654752f));
            C[(size_t)r * N + c] = vv;
        }
    }
}

// ---------------------------------------------------------------------------
// Sparse (radius-3) attention: one warp per (b, n, head), online softmax
// over at most 29 in-bounds neighbors. Masked entries contribute exactly 0
// (reference uses -1e9 bias; exp underflows to 0 in fp32), so skipping them
// is exact.
// ---------------------------------------------------------------------------
__global__ void attn_kernel(const float* __restrict__ q,
                            const float* __restrict__ k,
                            const float* __restrict__ v,
                            float* __restrict__ o)
{
    int gw   = (blockIdx.x * blockDim.x + threadIdx.x) >> 5;
    int lane = threadIdx.x & 31;
    if (gw >= Bb * Nn * NH) return;

    int h = gw & (NH - 1);
    int n = (gw >> 3) % Nn;
    int b = gw / (NH * Nn);
    int y = n / HS, xq = n % HS;

    size_t qoff = ((size_t)(b * Nn + n)) * Cc + h * HD + lane;
    float qv = q[qoff];

    float mx = -1e30f, l = 0.f, acc = 0.f;
#pragma unroll
    for (int j = 0; j < 29; j++) {
        int ny = y + c_dy[j];
        int nx = xq + c_dx[j];
        if ((unsigned)ny < (unsigned)HS && (unsigned)nx < (unsigned)HS) {
            size_t base = ((size_t)(b * Nn + ny * HS + nx)) * Cc + h * HD + lane;
            float s = qv * k[base];
#pragma unroll
            for (int off = 16; off; off >>= 1)
                s += __shfl_xor_sync(0xffffffffu, s, off);
            s *= SCALE;
            float nm = fmaxf(mx, s);
            float corr = expf(mx - nm);
            float p = expf(s - nm);
            l = l * corr + p;
            acc = acc * corr + p * v[base];
            mx = nm;
        }
    }
    o[qoff] = acc / l;
}

// ---------------------------------------------------------------------------
// Launch
// ---------------------------------------------------------------------------
static float* symaddr(const void* sym)
{
    void* p = nullptr;
    cudaGetSymbolAddress(&p, sym);
    return (float*)p;
}

extern "C" void kernel_launch(void* const* d_in, const int* in_sizes, int n_in,
                              void* d_out, int out_size)
{
    const float* x    = (const float*)d_in[0];
    const float* x_kv = (const float*)d_in[1];
    const float* Wq   = (const float*)d_in[2];
    const float* bq   = (const float*)d_in[3];
    const float* Wk   = (const float*)d_in[4];
    const float* bk   = (const float*)d_in[5];
    const float* Wv   = (const float*)d_in[6];
    const float* bv   = (const float*)d_in[7];
    const float* Wp   = (const float*)d_in[8];
    const float* bp   = (const float*)d_in[9];
    const float* g1   = (const float*)d_in[10];
    const float* b1   = (const float*)d_in[11];
    const float* g2   = (const float*)d_in[12];
    const float* b2   = (const float*)d_in[13];
    const float* W1   = (const float*)d_in[14];
    const float* bm1  = (const float*)d_in[15];
    const float* W2   = (const float*)d_in[16];
    const float* bm2  = (const float*)d_in[17];
    float* out = (float*)d_out;

    float* h   = symaddr(g_h);
    float* hkv = symaddr(g_hkv);
    float* qb  = symaddr(g_q);
    float* kb  = symaddr(g_k);
    float* vb  = symaddr(g_v);
    float* att = symaddr(g_att);
    float* x2  = symaddr(g_x2);
    float* mb  = symaddr(g_m);
    float* tb  = symaddr(g_t);

    // LN1 on x and x_kv
    {
        int warpsPerBlock = 8;
        int blocks = (ROWS + warpsPerBlock - 1) / warpsPerBlock;
        ln_kernel<<<blocks, warpsPerBlock * 32>>>(x, g1, b1, h, ROWS);
        ln_kernel<<<blocks, warpsPerBlock * 32>>>(x_kv, g1, b1, hkv, ROWS);
    }

    // QKV projections
    {
        dim3 grid(Cc / 64, ROWS / 128);
        sgemm<0><<<grid, 256>>>(h,   Wq, bq, nullptr, qb, ROWS, Cc, Cc);
        sgemm<0><<<grid, 256>>>(hkv, Wk, bk, nullptr, kb, ROWS, Cc, Cc);
        sgemm<0><<<grid, 256>>>(hkv, Wv, bv, nullptr, vb, ROWS, Cc, Cc);
    }

    // Sparse local attention
    {
        int totalWarps = Bb * Nn * NH;           // 73728
        int blocks = totalWarps / 8;             // 9216 (exact)
        attn_kernel<<<blocks, 256>>>(qb, kb, vb, att);
    }

    // Output projection + residual:  x2 = x + att @ Wp + bp
    {
        dim3 grid(Cc / 64, ROWS / 128);
        sgemm<1><<<grid, 256>>>(att, Wp, bp, x, x2, ROWS, Cc, Cc);
    }

    // LN2
    {
        int blocks = ROWS / 8;
        ln_kernel<<<blocks, 256>>>(x2, g2, b2, mb, ROWS);
    }

    // MLP: t = gelu(m @ W1 + bm1);  out = x2 + t @ W2 + bm2
    {
        dim3 grid1(HID / 64, ROWS / 128);
        sgemm<2><<<grid1, 256>>>(mb, W1, bm1, nullptr, tb, ROWS, HID, Cc);
        dim3 grid2(Cc / 64, ROWS / 128);
        sgemm<1><<<grid2, 256>>>(tb, W2, bm2, x2, out, ROWS, Cc, HID);
    }
}

// round 3
// speedup vs baseline: 1.7346x; 1.7346x over previous
#include <cuda_runtime.h>
#include <cuda_bf16.h>
#include <math.h>
#include <cstdint>

// ---------------------------------------------------------------------------
// Problem constants
// ---------------------------------------------------------------------------
static constexpr int Bb   = 4;
static constexpr int Nn   = 2304;      // 48*48
static constexpr int Cc   = 256;
static constexpr int NH   = 8;
static constexpr int HD   = 32;
static constexpr int HS   = 48;
static constexpr int HID  = 4 * Cc;    // 1024
static constexpr int ROWS = Bb * Nn;   // 9216
static constexpr float SCALE = 0.17677669529663687f; // 32^-0.5

// Neighbor offsets with dy*dy+dx*dx <= 9  (29 of them)
__constant__ int c_dy[29] = {-3,-2,-2,-2,-2,-2,-1,-1,-1,-1,-1, 0,0,0,0,0,0,0, 1,1,1,1,1, 2,2,2,2,2, 3};
__constant__ int c_dx[29] = { 0,-2,-1, 0, 1, 2,-2,-1, 0, 1, 2,-3,-2,-1,0,1,2,3,-2,-1,0,1,2,-2,-1,0,1,2, 0};

// ---------------------------------------------------------------------------
// Scratch (no cudaMalloc allowed)
// ---------------------------------------------------------------------------
using bf = __nv_bfloat16;
__device__ __align__(16) bf g_h_hi  [ROWS * Cc];
__device__ __align__(16) bf g_h_lo  [ROWS * Cc];
__device__ __align__(16) bf g_hk_hi [ROWS * Cc];
__device__ __align__(16) bf g_hk_lo [ROWS * Cc];
__device__ __align__(16) float g_q  [ROWS * Cc];
__device__ __align__(16) float g_k  [ROWS * Cc];
__device__ __align__(16) float g_v  [ROWS * Cc];
__device__ __align__(16) bf g_at_hi [ROWS * Cc];
__device__ __align__(16) bf g_at_lo [ROWS * Cc];
__device__ __align__(16) float g_x2 [ROWS * Cc];
__device__ __align__(16) bf g_m_hi  [ROWS * Cc];
__device__ __align__(16) bf g_m_lo  [ROWS * Cc];
__device__ __align__(16) bf g_t_hi  [ROWS * HID];
__device__ __align__(16) bf g_t_lo  [ROWS * HID];
// transposed + split weights: [N, K] layout
__device__ __align__(16) bf g_wq_hi [Cc * Cc];
__device__ __align__(16) bf g_wq_lo [Cc * Cc];
__device__ __align__(16) bf g_wk_hi [Cc * Cc];
__device__ __align__(16) bf g_wk_lo [Cc * Cc];
__device__ __align__(16) bf g_wv_hi [Cc * Cc];
__device__ __align__(16) bf g_wv_lo [Cc * Cc];
__device__ __align__(16) bf g_wp_hi [Cc * Cc];
__device__ __align__(16) bf g_wp_lo [Cc * Cc];
__device__ __align__(16) bf g_w1_hi [HID * Cc];
__device__ __align__(16) bf g_w1_lo [HID * Cc];
__device__ __align__(16) bf g_w2_hi [Cc * HID];
__device__ __align__(16) bf g_w2_lo [Cc * HID];

// ---------------------------------------------------------------------------
// PTX helpers (base-ISA only: mma.sync / ldmatrix / cp.async)
// ---------------------------------------------------------------------------
__device__ __forceinline__ uint32_t smem_u32(const void* p) {
    uint32_t a;
    asm("{ .reg .u64 t; cvta.to.shared.u64 t, %1; cvt.u32.u64 %0, t; }" : "=r"(a) : "l"(p));
    return a;
}
__device__ __forceinline__ void ldsm_x4(uint32_t* r, uint32_t addr) {
    asm volatile("ldmatrix.sync.aligned.m8n8.x4.shared.b16 {%0,%1,%2,%3}, [%4];"
        : "=r"(r[0]), "=r"(r[1]), "=r"(r[2]), "=r"(r[3]) : "r"(addr));
}
__device__ __forceinline__ void mma16816(float* d, const uint32_t* a, const uint32_t* b2) {
    asm volatile("mma.sync.aligned.m16n8k16.row.col.f32.bf16.bf16.f32 "
        "{%0,%1,%2,%3}, {%4,%5,%6,%7}, {%8,%9}, {%0,%1,%2,%3};"
        : "+f"(d[0]), "+f"(d[1]), "+f"(d[2]), "+f"(d[3])
        : "r"(a[0]), "r"(a[1]), "r"(a[2]), "r"(a[3]), "r"(b2[0]), "r"(b2[1]));
}
#define CP16(dst, src) \
    asm volatile("cp.async.cg.shared.global [%0], [%1], 16;" :: "r"(dst), "l"(src))
#define CP_COMMIT()  asm volatile("cp.async.commit_group;" ::: "memory")
#define CP_WAIT0()   asm volatile("cp.async.wait_group 0;" ::: "memory")
#define CP_WAIT1()   asm volatile("cp.async.wait_group 1;" ::: "memory")

// ---------------------------------------------------------------------------
// Weight transpose + bf16 hi/lo split: W[K,N] f32 -> T_hi/T_lo [N,K] bf16
// ---------------------------------------------------------------------------
__global__ void convw(const float* __restrict__ W,
                      bf* __restrict__ Th, bf* __restrict__ Tl, int K, int N)
{
    int idx = blockIdx.x * 256 + threadIdx.x;
    if (idx >= K * N) return;
    int k = idx / N, n = idx % N;
    float w = W[idx];
    bf h = __float2bfloat16(w);
    Th[(size_t)n * K + k] = h;
    Tl[(size_t)n * K + k] = __float2bfloat16(w - __bfloat162float(h));
}

// ---------------------------------------------------------------------------
// LayerNorm: one warp per row of 256; emits bf16 hi/lo
// ---------------------------------------------------------------------------
__global__ void ln_kernel(const float* __restrict__ x,
                          const float* __restrict__ g,
                          const float* __restrict__ b,
                          bf* __restrict__ oh, bf* __restrict__ ol, int rows)
{
    int gw   = (blockIdx.x * blockDim.x + threadIdx.x) >> 5;
    int lane = threadIdx.x & 31;
    if (gw >= rows) return;
    const float* xr = x + (size_t)gw * Cc;
    float f[8], s = 0.f, ss = 0.f;
#pragma unroll
    for (int i = 0; i < 8; i++) {
        f[i] = xr[lane + 32 * i];
        s  += f[i];
        ss += f[i] * f[i];
    }
#pragma unroll
    for (int off = 16; off; off >>= 1) {
        s  += __shfl_xor_sync(0xffffffffu, s,  off);
        ss += __shfl_xor_sync(0xffffffffu, ss, off);
    }
    float mu  = s * (1.f / 256.f);
    float var = ss * (1.f / 256.f) - mu * mu;
    float inv = rsqrtf(var + 1e-6f);
    size_t base = (size_t)gw * Cc;
#pragma unroll
    for (int i = 0; i < 8; i++) {
        int c = lane + 32 * i;
        float v = (f[i] - mu) * inv * g[c] + b[c];
        bf hv = __float2bfloat16(v);
        oh[base + c] = hv;
        ol[base + c] = __float2bfloat16(v - __bfloat162float(hv));
    }
}

// ---------------------------------------------------------------------------
// Sparse (radius-3) attention: one warp per (b, n, head); emits bf16 hi/lo
// ---------------------------------------------------------------------------
__global__ void attn_kernel(const float* __restrict__ q,
                            const float* __restrict__ k,
                            const float* __restrict__ v,
                            bf* __restrict__ oh, bf* __restrict__ ol)
{
    int gw   = (blockIdx.x * blockDim.x + threadIdx.x) >> 5;
    int lane = threadIdx.x & 31;
    if (gw >= Bb * Nn * NH) return;

    int h = gw & (NH - 1);
    int n = (gw >> 3) % Nn;
    int b = gw / (NH * Nn);
    int y = n / HS, xq = n % HS;

    size_t qoff = ((size_t)(b * Nn + n)) * Cc + h * HD + lane;
    float qv = q[qoff];

    float mx = -1e30f, l = 0.f, acc = 0.f;
#pragma unroll
    for (int j = 0; j < 29; j++) {
        int ny = y + c_dy[j];
        int nx = xq + c_dx[j];
        if ((unsigned)ny < (unsigned)HS && (unsigned)nx < (unsigned)HS) {
            size_t base = ((size_t)(b * Nn + ny * HS + nx)) * Cc + h * HD + lane;
            float s = qv * k[base];
#pragma unroll
            for (int off = 16; off; off >>= 1)
                s += __shfl_xor_sync(0xffffffffu, s, off);
            s *= SCALE;
            float nm = fmaxf(mx, s);
            float corr = expf(mx - nm);
            float p = expf(s - nm);
            l = l * corr + p;
            acc = acc * corr + p * v[base];
            mx = nm;
        }
    }
    float res = acc / l;
    bf hv = __float2bfloat16(res);
    oh[qoff] = hv;
    ol[qoff] = __float2bfloat16(res - __bfloat162float(hv));
}

// ---------------------------------------------------------------------------
// Split-bf16 GEMM via mma.sync (HMMA).
// C[M,N] = (Ah+Al)[M,K] @ (Bh+Bl)^T[N,K]   (Al*Bl dropped)
// CTA tile 128x64, 8 warps (4x2), warp tile 32x32, BK=64,
// cp.async double-buffered smem, XOR-swizzled 128B rows.
// EPI: 0 -> Co = acc+bias ; 1 -> Co = acc+bias+res ; 2 -> gelu -> bf16 hi/lo
// ---------------------------------------------------------------------------
static constexpr int SMBUF = 49152;       // Ah 16K | Al 16K | Bh 8K | Bl 8K
static constexpr int SMTOT = 2 * SMBUF;   // 96 KB

template <int EPI>
__global__ void __launch_bounds__(256) mma_gemm(
    const bf* __restrict__ Ah, const bf* __restrict__ Al,
    const bf* __restrict__ Bh, const bf* __restrict__ Bl,
    const float* __restrict__ bias, const float* __restrict__ res,
    float* __restrict__ Co, bf* __restrict__ oH, bf* __restrict__ oL,
    int M, int N, int K)
{
    extern __shared__ __align__(1024) char smc[];
    const uint32_t sbase = smem_u32(smc);
    const int tid  = threadIdx.x;
    const int lane = tid & 31;
    const int wid  = tid >> 5;
    const int tm = blockIdx.y, tn = blockIdx.x;
    const int wm = wid >> 1, wn = wid & 1;   // 4 x 2 warp grid

    const size_t strK = (size_t)K * 2;       // bytes per row
    const char* pAh = (const char*)Ah + ((size_t)tm * 128) * strK;
    const char* pAl = (const char*)Al + ((size_t)tm * 128) * strK;
    const char* pBh = (const char*)Bh + ((size_t)tn * 64)  * strK;
    const char* pBl = (const char*)Bl + ((size_t)tn * 64)  * strK;

    const int nCh = K >> 6;

    // ---- async tile loader -------------------------------------------------
    auto load_tiles = [&](int buf, int ch) {
        uint32_t d0 = sbase + buf * SMBUF;
        size_t koff = (size_t)ch * 128;      // 64 bf16 = 128 B
        // A: 2048 granules of 16B (hi then lo)
#pragma unroll
        for (int i = 0; i < 8; i++) {
            int g = i * 256 + tid;
            int prec = g >> 10;
            int gg = g & 1023;
            int r = gg >> 3, c = gg & 7;
            const char* src = (prec ? pAl : pAh) + (size_t)r * strK + koff + (c << 4);
            uint32_t dst = d0 + prec * 16384 + (r << 7) + (((c) ^ (r & 7)) << 4);
            CP16(dst, src);
        }
        // B: 1024 granules (hi then lo)
#pragma unroll
        for (int i = 0; i < 4; i++) {
            int g = i * 256 + tid;
            int prec = g >> 9;
            int gg = g & 511;
            int r = gg >> 3, c = gg & 7;
            const char* src = (prec ? pBl : pBh) + (size_t)r * strK + koff + (c << 4);
            uint32_t dst = d0 + 32768 + prec * 8192 + (r << 7) + (((c) ^ (r & 7)) << 4);
            CP16(dst, src);
        }
        CP_COMMIT();
    };

    // ldmatrix per-lane row mapping (same pattern for A and B)
    const int rl = lane & 15;       // row within 16-row group
    const int kc = lane >> 4;       // k-chunk half (0/1)

    // A rows for the two m16 fragments of this warp
    const int rowA0 = wm * 32 + rl;
    const int rowA1 = wm * 32 + 16 + rl;
    // B rows for the two n16 groups of this warp
    const int rowB0 = wn * 32 + rl;
    const int rowB1 = wn * 32 + 16 + rl;

    float acc[2][4][4] = {};

    load_tiles(0, 0);

    for (int ch = 0; ch < nCh; ch++) {
        if (ch + 1 < nCh) { load_tiles((ch + 1) & 1, ch + 1); CP_WAIT1(); }
        else             { CP_WAIT0(); }
        __syncthreads();

        uint32_t aB = sbase + (ch & 1) * SMBUF;
        uint32_t bB = aB + 32768;

#pragma unroll
        for (int k16 = 0; k16 < 4; k16++) {
            const int k2 = k16 * 2 + kc;
            uint32_t ah[2][4], al[2][4], bh[2][4], bl[2][4];
            {
                uint32_t adr0 = aB + (rowA0 << 7) + ((k2 ^ (rowA0 & 7)) << 4);
                uint32_t adr1 = aB + (rowA1 << 7) + ((k2 ^ (rowA1 & 7)) << 4);
                ldsm_x4(ah[0], adr0);
                ldsm_x4(ah[1], adr1);
                ldsm_x4(al[0], adr0 + 16384);
                ldsm_x4(al[1], adr1 + 16384);
            }
            {
                uint32_t adr0 = bB + (rowB0 << 7) + ((k2 ^ (rowB0 & 7)) << 4);
                uint32_t adr1 = bB + (rowB1 << 7) + ((k2 ^ (rowB1 & 7)) << 4);
                ldsm_x4(bh[0], adr0);
                ldsm_x4(bh[1], adr1);
                ldsm_x4(bl[0], adr0 + 8192);
                ldsm_x4(bl[1], adr1 + 8192);
            }
#pragma unroll
            for (int mi = 0; mi < 2; mi++) {
#pragma unroll
                for (int j = 0; j < 4; j++) {
                    uint32_t bh2[2] = { bh[j >> 1][j & 1], bh[j >> 1][2 + (j & 1)] };
                    uint32_t bl2[2] = { bl[j >> 1][j & 1], bl[j >> 1][2 + (j & 1)] };
                    mma16816(acc[mi][j], ah[mi], bh2);
                    mma16816(acc[mi][j], al[mi], bh2);
                    mma16816(acc[mi][j], ah[mi], bl2);
                }
            }
        }
        __syncthreads();
    }

    // ---- epilogue -----------------------------------------------------------
    const int rbase = tm * 128 + wm * 32 + (lane >> 2);
    const int cbase = tn * 64 + wn * 32 + (lane & 3) * 2;
#pragma unroll
    for (int mi = 0; mi < 2; mi++) {
#pragma unroll
        for (int j = 0; j < 4; j++) {
            int row0 = rbase + mi * 16;
            int col  = cbase + j * 8;
            float b0 = bias[col], b1 = bias[col + 1];
            float v00 = acc[mi][j][0] + b0;
            float v01 = acc[mi][j][1] + b1;
            float v10 = acc[mi][j][2] + b0;
            float v11 = acc[mi][j][3] + b1;
            size_t i0 = (size_t)row0 * N + col;
            size_t i1 = (size_t)(row0 + 8) * N + col;
            if (EPI == 0) {
                *(float2*)(Co + i0) = make_float2(v00, v01);
                *(float2*)(Co + i1) = make_float2(v10, v11);
            } else if (EPI == 1) {
                float2 r0 = *(const float2*)(res + i0);
                float2 r1 = *(const float2*)(res + i1);
                *(float2*)(Co + i0) = make_float2(v00 + r0.x, v01 + r0.y);
                *(float2*)(Co + i1) = make_float2(v10 + r1.x, v11 + r1.y);
            } else {
                const float IS2 = 0.70710678118654752f;
                v00 = 0.5f * v00 * (1.f + erff(v00 * IS2));
                v01 = 0.5f * v01 * (1.f + erff(v01 * IS2));
                v10 = 0.5f * v10 * (1.f + erff(v10 * IS2));
                v11 = 0.5f * v11 * (1.f + erff(v11 * IS2));
                bf h00 = __float2bfloat16(v00), h01 = __float2bfloat16(v01);
                bf h10 = __float2bfloat16(v10), h11 = __float2bfloat16(v11);
                __nv_bfloat162 hh0; hh0.x = h00; hh0.y = h01;
                __nv_bfloat162 hh1; hh1.x = h10; hh1.y = h11;
                *(__nv_bfloat162*)(oH + i0) = hh0;
                *(__nv_bfloat162*)(oH + i1) = hh1;
                __nv_bfloat162 ll0, ll1;
                ll0.x = __float2bfloat16(v00 - __bfloat162float(h00));
                ll0.y = __float2bfloat16(v01 - __bfloat162float(h01));
                ll1.x = __float2bfloat16(v10 - __bfloat162float(h10));
                ll1.y = __float2bfloat16(v11 - __bfloat162float(h11));
                *(__nv_bfloat162*)(oL + i0) = ll0;
                *(__nv_bfloat162*)(oL + i1) = ll1;
            }
        }
    }
}

// ---------------------------------------------------------------------------
// Launch
// ---------------------------------------------------------------------------
template <typename T>
static T* symaddr(const void* sym)
{
    void* p = nullptr;
    cudaGetSymbolAddress(&p, sym);
    return (T*)p;
}

extern "C" void kernel_launch(void* const* d_in, const int* in_sizes, int n_in,
                              void* d_out, int out_size)
{
    const float* x    = (const float*)d_in[0];
    const float* x_kv = (const float*)d_in[1];
    const float* Wq   = (const float*)d_in[2];
    const float* bq   = (const float*)d_in[3];
    const float* Wk   = (const float*)d_in[4];
    const float* bk   = (const float*)d_in[5];
    const float* Wv   = (const float*)d_in[6];
    const float* bv   = (const float*)d_in[7];
    const float* Wp   = (const float*)d_in[8];
    const float* bp   = (const float*)d_in[9];
    const float* g1   = (const float*)d_in[10];
    const float* b1   = (const float*)d_in[11];
    const float* g2   = (const float*)d_in[12];
    const float* b2   = (const float*)d_in[13];
    const float* W1   = (const float*)d_in[14];
    const float* bm1  = (const float*)d_in[15];
    const float* W2   = (const float*)d_in[16];
    const float* bm2  = (const float*)d_in[17];
    float* out = (float*)d_out;

    bf* h_hi  = symaddr<bf>(g_h_hi);   bf* h_lo  = symaddr<bf>(g_h_lo);
    bf* hk_hi = symaddr<bf>(g_hk_hi);  bf* hk_lo = symaddr<bf>(g_hk_lo);
    float* qb = symaddr<float>(g_q);
    float* kb = symaddr<float>(g_k);
    float* vb = symaddr<float>(g_v);
    bf* at_hi = symaddr<bf>(g_at_hi);  bf* at_lo = symaddr<bf>(g_at_lo);
    float* x2 = symaddr<float>(g_x2);
    bf* m_hi  = symaddr<bf>(g_m_hi);   bf* m_lo  = symaddr<bf>(g_m_lo);
    bf* t_hi  = symaddr<bf>(g_t_hi);   bf* t_lo  = symaddr<bf>(g_t_lo);
    bf* wq_hi = symaddr<bf>(g_wq_hi);  bf* wq_lo = symaddr<bf>(g_wq_lo);
    bf* wk_hi = symaddr<bf>(g_wk_hi);  bf* wk_lo = symaddr<bf>(g_wk_lo);
    bf* wv_hi = symaddr<bf>(g_wv_hi);  bf* wv_lo = symaddr<bf>(g_wv_lo);
    bf* wp_hi = symaddr<bf>(g_wp_hi);  bf* wp_lo = symaddr<bf>(g_wp_lo);
    bf* w1_hi = symaddr<bf>(g_w1_hi);  bf* w1_lo = symaddr<bf>(g_w1_lo);
    bf* w2_hi = symaddr<bf>(g_w2_hi);  bf* w2_lo = symaddr<bf>(g_w2_lo);

    static bool attrSet = false;
    if (!attrSet) {
        cudaFuncSetAttribute(mma_gemm<0>, cudaFuncAttributeMaxDynamicSharedMemorySize, SMTOT);
        cudaFuncSetAttribute(mma_gemm<1>, cudaFuncAttributeMaxDynamicSharedMemorySize, SMTOT);
        cudaFuncSetAttribute(mma_gemm<2>, cudaFuncAttributeMaxDynamicSharedMemorySize, SMTOT);
        attrSet = true;
    }

    // Weight transpose + split
    {
        int nC = Cc * Cc, nH = Cc * HID;
        convw<<<(nC + 255) / 256, 256>>>(Wq, wq_hi, wq_lo, Cc, Cc);
        convw<<<(nC + 255) / 256, 256>>>(Wk, wk_hi, wk_lo, Cc, Cc);
        convw<<<(nC + 255) / 256, 256>>>(Wv, wv_hi, wv_lo, Cc, Cc);
        convw<<<(nC + 255) / 256, 256>>>(Wp, wp_hi, wp_lo, Cc, Cc);
        convw<<<(nH + 255) / 256, 256>>>(W1, w1_hi, w1_lo, Cc, HID);
        convw<<<(nH + 255) / 256, 256>>>(W2, w2_hi, w2_lo, HID, Cc);
    }

    // LN1 on x and x_kv (-> bf16 hi/lo)
    {
        int blocks = ROWS / 8;
        ln_kernel<<<blocks, 256>>>(x,    g1, b1, h_hi,  h_lo,  ROWS);
        ln_kernel<<<blocks, 256>>>(x_kv, g1, b1, hk_hi, hk_lo, ROWS);
    }

    // QKV projections (fp32 out)
    {
        dim3 grid(Cc / 64, ROWS / 128);
        mma_gemm<0><<<grid, 256, SMTOT>>>(h_hi,  h_lo,  wq_hi, wq_lo, bq, nullptr, qb, nullptr, nullptr, ROWS, Cc, Cc);
        mma_gemm<0><<<grid, 256, SMTOT>>>(hk_hi, hk_lo, wk_hi, wk_lo, bk, nullptr, kb, nullptr, nullptr, ROWS, Cc, Cc);
        mma_gemm<0><<<grid, 256, SMTOT>>>(hk_hi, hk_lo, wv_hi, wv_lo, bv, nullptr, vb, nullptr, nullptr, ROWS, Cc, Cc);
    }

    // Sparse local attention (-> bf16 hi/lo)
    {
        int totalWarps = Bb * Nn * NH;  // 73728
        attn_kernel<<<totalWarps / 8, 256>>>(qb, kb, vb, at_hi, at_lo);
    }

    // x2 = x + att @ Wp + bp
    {
        dim3 grid(Cc / 64, ROWS / 128);
        mma_gemm<1><<<grid, 256, SMTOT>>>(at_hi, at_lo, wp_hi, wp_lo, bp, x, x2, nullptr, nullptr, ROWS, Cc, Cc);
    }

    // LN2 (-> bf16 hi/lo)
    ln_kernel<<<ROWS / 8, 256>>>(x2, g2, b2, m_hi, m_lo, ROWS);

    // MLP: t = gelu(m @ W1 + bm1) (-> bf16 hi/lo); out = x2 + t @ W2 + bm2
    {
        dim3 grid1(HID / 64, ROWS / 128);
        mma_gemm<2><<<grid1, 256, SMTOT>>>(m_hi, m_lo, w1_hi, w1_lo, bm1, nullptr, nullptr, t_hi, t_lo, ROWS, HID, Cc);
        dim3 grid2(Cc / 64, ROWS / 128);
        mma_gemm<1><<<grid2, 256, SMTOT>>>(t_hi, t_lo, w2_hi, w2_lo, bm2, x2, out, nullptr, nullptr, ROWS, Cc, HID);
    }
}

// round 4
// speedup vs baseline: 1.8067x; 1.0416x over previous
#include <cuda_runtime.h>
#include <cuda_bf16.h>
#include <math.h>
#include <cstdint>

// ---------------------------------------------------------------------------
// Problem constants
// ---------------------------------------------------------------------------
static constexpr int Bb   = 4;
static constexpr int Nn   = 2304;      // 48*48
static constexpr int Cc   = 256;
static constexpr int NH   = 8;
static constexpr int HD   = 32;
static constexpr int HS   = 48;
static constexpr int HID  = 4 * Cc;    // 1024
static constexpr int ROWS = Bb * Nn;   // 9216
static constexpr float SCALE = 0.17677669529663687f; // 32^-0.5

// Neighbor offsets with dy*dy+dx*dx <= 9  (29 of them)
__constant__ int c_dy[29] = {-3,-2,-2,-2,-2,-2,-1,-1,-1,-1,-1, 0,0,0,0,0,0,0, 1,1,1,1,1, 2,2,2,2,2, 3};
__constant__ int c_dx[29] = { 0,-2,-1, 0, 1, 2,-2,-1, 0, 1, 2,-3,-2,-1,0,1,2,3,-2,-1,0,1,2,-2,-1,0,1,2, 0};

// ---------------------------------------------------------------------------
// Scratch (no cudaMalloc allowed)
// ---------------------------------------------------------------------------
using bf = __nv_bfloat16;
__device__ __align__(16) bf g_h_hi  [ROWS * Cc];
__device__ __align__(16) bf g_h_lo  [ROWS * Cc];
__device__ __align__(16) bf g_hk_hi [ROWS * Cc];
__device__ __align__(16) bf g_hk_lo [ROWS * Cc];
__device__ __align__(16) float g_q  [ROWS * Cc];
__device__ __align__(16) float g_k  [ROWS * Cc];
__device__ __align__(16) float g_v  [ROWS * Cc];
__device__ __align__(16) bf g_at_hi [ROWS * Cc];
__device__ __align__(16) bf g_at_lo [ROWS * Cc];
__device__ __align__(16) float g_x2 [ROWS * Cc];
__device__ __align__(16) bf g_m_hi  [ROWS * Cc];
__device__ __align__(16) bf g_m_lo  [ROWS * Cc];
__device__ __align__(16) bf g_t_hi  [ROWS * HID];
__device__ __align__(16) bf g_t_lo  [ROWS * HID];
// transposed + split weights: [N, K] layout
__device__ __align__(16) bf g_wq_hi [Cc * Cc];
__device__ __align__(16) bf g_wq_lo [Cc * Cc];
__device__ __align__(16) bf g_wk_hi [Cc * Cc];
__device__ __align__(16) bf g_wk_lo [Cc * Cc];
__device__ __align__(16) bf g_wv_hi [Cc * Cc];
__device__ __align__(16) bf g_wv_lo [Cc * Cc];
__device__ __align__(16) bf g_wp_hi [Cc * Cc];
__device__ __align__(16) bf g_wp_lo [Cc * Cc];
__device__ __align__(16) bf g_w1_hi [HID * Cc];
__device__ __align__(16) bf g_w1_lo [HID * Cc];
__device__ __align__(16) bf g_w2_hi [Cc * HID];
__device__ __align__(16) bf g_w2_lo [Cc * HID];

// ---------------------------------------------------------------------------
// PTX helpers (base-ISA only: mma.sync / ldmatrix / cp.async)
// ---------------------------------------------------------------------------
__device__ __forceinline__ uint32_t smem_u32(const void* p) {
    uint32_t a;
    asm("{ .reg .u64 t; cvta.to.shared.u64 t, %1; cvt.u32.u64 %0, t; }" : "=r"(a) : "l"(p));
    return a;
}
__device__ __forceinline__ void ldsm_x4(uint32_t* r, uint32_t addr) {
    asm volatile("ldmatrix.sync.aligned.m8n8.x4.shared.b16 {%0,%1,%2,%3}, [%4];"
        : "=r"(r[0]), "=r"(r[1]), "=r"(r[2]), "=r"(r[3]) : "r"(addr));
}
__device__ __forceinline__ void mma16816(float* d, const uint32_t* a, uint32_t b0, uint32_t b1) {
    asm volatile("mma.sync.aligned.m16n8k16.row.col.f32.bf16.bf16.f32 "
        "{%0,%1,%2,%3}, {%4,%5,%6,%7}, {%8,%9}, {%0,%1,%2,%3};"
        : "+f"(d[0]), "+f"(d[1]), "+f"(d[2]), "+f"(d[3])
        : "r"(a[0]), "r"(a[1]), "r"(a[2]), "r"(a[3]), "r"(b0), "r"(b1));
}
#define CP16(dst, src) \
    asm volatile("cp.async.cg.shared.global [%0], [%1], 16;" :: "r"(dst), "l"(src))
#define CP_COMMIT()  asm volatile("cp.async.commit_group;" ::: "memory")
#define CP_WAIT0()   asm volatile("cp.async.wait_group 0;" ::: "memory")
#define CP_WAIT1()   asm volatile("cp.async.wait_group 1;" ::: "memory")

// ---------------------------------------------------------------------------
// All-in-one weight transpose + bf16 hi/lo split (coalesced, smem-tiled).
// W[K,N] f32 -> T_hi/T_lo [N,K] bf16.  One 32x32 tile per block.
// Blocks: [0,256) -> Wq/Wk/Wv/Wp (64 tiles each); [256,512) -> W1; [512,768) -> W2
// ---------------------------------------------------------------------------
__global__ void __launch_bounds__(256) convw_all(
    const float* __restrict__ Wq, const float* __restrict__ Wk,
    const float* __restrict__ Wv, const float* __restrict__ Wp,
    const float* __restrict__ W1, const float* __restrict__ W2,
    bf* qh, bf* ql, bf* kh, bf* kl, bf* vh, bf* vl,
    bf* ph, bf* pl, bf* h1h, bf* h1l, bf* h2h, bf* h2l)
{
    __shared__ float t[32][33];
    int bid = blockIdx.x;
    const float* W; bf* Th; bf* Tl; int K, N, tile;
    if (bid < 256) {
        int w = bid >> 6; tile = bid & 63; K = 256; N = 256;
        if      (w == 0) { W = Wq; Th = qh; Tl = ql; }
        else if (w == 1) { W = Wk; Th = kh; Tl = kl; }
        else if (w == 2) { W = Wv; Th = vh; Tl = vl; }
        else             { W = Wp; Th = ph; Tl = pl; }
    } else if (bid < 512) {
        W = W1; Th = h1h; Tl = h1l; K = 256; N = 1024; tile = bid - 256;
    } else {
        W = W2; Th = h2h; Tl = h2l; K = 1024; N = 256; tile = bid - 512;
    }
    int ntn = N >> 5;
    int tk = tile / ntn, tn = tile % ntn;
    int tx = threadIdx.x & 31, ty = threadIdx.x >> 5;
#pragma unroll
    for (int i = 0; i < 4; i++) {
        int r = ty + i * 8;
        t[r][tx] = W[(size_t)(tk * 32 + r) * N + tn * 32 + tx];
    }
    __syncthreads();
#pragma unroll
    for (int i = 0; i < 4; i++) {
        int r = ty + i * 8;
        float wv = t[tx][r];
        size_t o = (size_t)(tn * 32 + r) * K + tk * 32 + tx;
        bf h = __float2bfloat16(wv);
        Th[o] = h;
        Tl[o] = __float2bfloat16(wv - __bfloat162float(h));
    }
}

// ---------------------------------------------------------------------------
// LayerNorm: one warp per row of 256; emits bf16 hi/lo
// ---------------------------------------------------------------------------
__global__ void ln_kernel(const float* __restrict__ x,
                          const float* __restrict__ g,
                          const float* __restrict__ b,
                          bf* __restrict__ oh, bf* __restrict__ ol, int rows)
{
    int gw   = (blockIdx.x * blockDim.x + threadIdx.x) >> 5;
    int lane = threadIdx.x & 31;
    if (gw >= rows) return;
    const float* xr = x + (size_t)gw * Cc;
    float f[8], s = 0.f, ss = 0.f;
#pragma unroll
    for (int i = 0; i < 8; i++) {
        f[i] = xr[lane + 32 * i];
        s  += f[i];
        ss += f[i] * f[i];
    }
#pragma unroll
    for (int off = 16; off; off >>= 1) {
        s  += __shfl_xor_sync(0xffffffffu, s,  off);
        ss += __shfl_xor_sync(0xffffffffu, ss, off);
    }
    float mu  = s * (1.f / 256.f);
    float var = ss * (1.f / 256.f) - mu * mu;
    float inv = rsqrtf(var + 1e-6f);
    size_t base = (size_t)gw * Cc;
#pragma unroll
    for (int i = 0; i < 8; i++) {
        int c = lane + 32 * i;
        float v = (f[i] - mu) * inv * g[c] + b[c];
        bf hv = __float2bfloat16(v);
        oh[base + c] = hv;
        ol[base + c] = __float2bfloat16(v - __bfloat162float(hv));
    }
}

// ---------------------------------------------------------------------------
// Sparse (radius-3) attention: one warp per (b, n, head); emits bf16 hi/lo
// ---------------------------------------------------------------------------
__global__ void attn_kernel(const float* __restrict__ q,
                            const float* __restrict__ k,
                            const float* __restrict__ v,
                            bf* __restrict__ oh, bf* __restrict__ ol)
{
    int gw   = (blockIdx.x * blockDim.x + threadIdx.x) >> 5;
    int lane = threadIdx.x & 31;
    if (gw >= Bb * Nn * NH) return;

    int h = gw & (NH - 1);
    int n = (gw >> 3) % Nn;
    int b = gw / (NH * Nn);
    int y = n / HS, xq = n % HS;

    size_t qoff = ((size_t)(b * Nn + n)) * Cc + h * HD + lane;
    float qv = q[qoff];

    float mx = -1e30f, l = 0.f, acc = 0.f;
#pragma unroll
    for (int j = 0; j < 29; j++) {
        int ny = y + c_dy[j];
        int nx = xq + c_dx[j];
        if ((unsigned)ny < (unsigned)HS && (unsigned)nx < (unsigned)HS) {
            size_t base = ((size_t)(b * Nn + ny * HS + nx)) * Cc + h * HD + lane;
            float s = qv * k[base];
#pragma unroll
            for (int off = 16; off; off >>= 1)
                s += __shfl_xor_sync(0xffffffffu, s, off);
            s *= SCALE;
            float nm = fmaxf(mx, s);
            float corr = expf(mx - nm);
            float p = expf(s - nm);
            l = l * corr + p;
            acc = acc * corr + p * v[base];
            mx = nm;
        }
    }
    float res = acc / l;
    bf hv = __float2bfloat16(res);
    oh[qoff] = hv;
    ol[qoff] = __float2bfloat16(res - __bfloat162float(hv));
}

// ---------------------------------------------------------------------------
// Split-bf16 GEMM via mma.sync (HMMA).
// C[M,N] = (Ah+Al)[M,K] @ (Bh+Bl)^T[N,K]   (Al*Bl dropped)
// CTA tile 128x128, 8 warps (2x4), warp tile 64x32, BK=64,
// cp.async double-buffered smem, XOR-swizzled 128B rows.
// EPI: 0 -> Co = acc+bias ; 1 -> Co = acc+bias+res ; 2 -> gelu -> bf16 hi/lo
// ---------------------------------------------------------------------------
static constexpr int SMBUF = 65536;       // Ah 16K | Al 16K | Bh 16K | Bl 16K
static constexpr int SMTOT = 2 * SMBUF;   // 128 KB

template <int EPI>
__global__ void __launch_bounds__(256) mma_gemm(
    const bf* __restrict__ Ah, const bf* __restrict__ Al,
    const bf* __restrict__ Bh, const bf* __restrict__ Bl,
    const float* __restrict__ bias, const float* __restrict__ res,
    float* __restrict__ Co, bf* __restrict__ oH, bf* __restrict__ oL,
    int M, int N, int K)
{
    extern __shared__ __align__(1024) char smc[];
    const uint32_t sbase = smem_u32(smc);
    const int tid  = threadIdx.x;
    const int lane = tid & 31;
    const int wid  = tid >> 5;
    const int tm = blockIdx.y, tn = blockIdx.x;
    const int wm = wid >> 2, wn = wid & 3;   // 2 x 4 warp grid, warp tile 64x32

    const size_t strK = (size_t)K * 2;       // bytes per row
    const char* pAh = (const char*)Ah + ((size_t)tm * 128) * strK;
    const char* pAl = (const char*)Al + ((size_t)tm * 128) * strK;
    const char* pBh = (const char*)Bh + ((size_t)tn * 128) * strK;
    const char* pBl = (const char*)Bl + ((size_t)tn * 128) * strK;

    const int nCh = K >> 6;

    // ---- async tile loader: 128 rows x 8 x 16B granules x 2 precisions, A & B
    auto load_tiles = [&](int buf, int ch) {
        uint32_t d0 = sbase + buf * SMBUF;
        size_t koff = (size_t)ch * 128;      // 64 bf16 = 128 B
#pragma unroll
        for (int i = 0; i < 8; i++) {
            int g = i * 256 + tid;
            int prec = g >> 10;
            int gg = g & 1023;
            int r = gg >> 3, c = gg & 7;
            const char* src = (prec ? pAl : pAh) + (size_t)r * strK + koff + (c << 4);
            uint32_t dst = d0 + prec * 16384 + (r << 7) + ((c ^ (r & 7)) << 4);
            CP16(dst, src);
        }
#pragma unroll
        for (int i = 0; i < 8; i++) {
            int g = i * 256 + tid;
            int prec = g >> 10;
            int gg = g & 1023;
            int r = gg >> 3, c = gg & 7;
            const char* src = (prec ? pBl : pBh) + (size_t)r * strK + koff + (c << 4);
            uint32_t dst = d0 + 32768 + prec * 16384 + (r << 7) + ((c ^ (r & 7)) << 4);
            CP16(dst, src);
        }
        CP_COMMIT();
    };

    const int rl = lane & 15;       // row within 16-row group
    const int kc = lane >> 4;       // k-chunk half (0/1)

    float acc[4][4][4] = {};

    load_tiles(0, 0);

    for (int ch = 0; ch < nCh; ch++) {
        if (ch + 1 < nCh) { load_tiles((ch + 1) & 1, ch + 1); CP_WAIT1(); }
        else             { CP_WAIT0(); }
        __syncthreads();

        uint32_t aB = sbase + (ch & 1) * SMBUF;
        uint32_t bB = aB + 32768;

#pragma unroll
        for (int k16 = 0; k16 < 4; k16++) {
            const int k2 = k16 * 2 + kc;
            uint32_t ah[4][4], al[4][4], bh[2][4], bl[2][4];
#pragma unroll
            for (int f = 0; f < 4; f++) {
                int rA = wm * 64 + f * 16 + rl;
                uint32_t adr = aB + (rA << 7) + ((k2 ^ (rA & 7)) << 4);
                ldsm_x4(ah[f], adr);
                ldsm_x4(al[f], adr + 16384);
            }
            {
                int rB0 = wn * 32 + rl, rB1 = wn * 32 + 16 + rl;
                uint32_t adr0 = bB + (rB0 << 7) + ((k2 ^ (rB0 & 7)) << 4);
                uint32_t adr1 = bB + (rB1 << 7) + ((k2 ^ (rB1 & 7)) << 4);
                ldsm_x4(bh[0], adr0);
                ldsm_x4(bh[1], adr1);
                ldsm_x4(bl[0], adr0 + 16384);
                ldsm_x4(bl[1], adr1 + 16384);
            }
            // 3 passes so each accumulator's dependent MMAs are well separated
#pragma unroll
            for (int f = 0; f < 4; f++)
#pragma unroll
                for (int j = 0; j < 4; j++)
                    mma16816(acc[f][j], ah[f], bh[j >> 1][j & 1], bh[j >> 1][2 + (j & 1)]);
#pragma unroll
            for (int f = 0; f < 4; f++)
#pragma unroll
                for (int j = 0; j < 4; j++)
                    mma16816(acc[f][j], al[f], bh[j >> 1][j & 1], bh[j >> 1][2 + (j & 1)]);
#pragma unroll
            for (int f = 0; f < 4; f++)
#pragma unroll
                for (int j = 0; j < 4; j++)
                    mma16816(acc[f][j], ah[f], bl[j >> 1][j & 1], bl[j >> 1][2 + (j & 1)]);
        }
        __syncthreads();
    }

    // ---- epilogue -----------------------------------------------------------
    const int rbase = tm * 128 + wm * 64 + (lane >> 2);
    const int cbase = tn * 128 + wn * 32 + (lane & 3) * 2;
#pragma unroll
    for (int f = 0; f < 4; f++) {
#pragma unroll
        for (int j = 0; j < 4; j++) {
            int row0 = rbase + f * 16;
            int col  = cbase + j * 8;
            float b0 = bias[col], b1 = bias[col + 1];
            float v00 = acc[f][j][0] + b0;
            float v01 = acc[f][j][1] + b1;
            float v10 = acc[f][j][2] + b0;
            float v11 = acc[f][j][3] + b1;
            size_t i0 = (size_t)row0 * N + col;
            size_t i1 = (size_t)(row0 + 8) * N + col;
            if (EPI == 0) {
                *(float2*)(Co + i0) = make_float2(v00, v01);
                *(float2*)(Co + i1) = make_float2(v10, v11);
            } else if (EPI == 1) {
                float2 r0 = *(const float2*)(res + i0);
                float2 r1 = *(const float2*)(res + i1);
                *(float2*)(Co + i0) = make_float2(v00 + r0.x, v01 + r0.y);
                *(float2*)(Co + i1) = make_float2(v10 + r1.x, v11 + r1.y);
            } else {
                const float IS2 = 0.70710678118654752f;
                v00 = 0.5f * v00 * (1.f + erff(v00 * IS2));
                v01 = 0.5f * v01 * (1.f + erff(v01 * IS2));
                v10 = 0.5f * v10 * (1.f + erff(v10 * IS2));
                v11 = 0.5f * v11 * (1.f + erff(v11 * IS2));
                bf h00 = __float2bfloat16(v00), h01 = __float2bfloat16(v01);
                bf h10 = __float2bfloat16(v10), h11 = __float2bfloat16(v11);
                __nv_bfloat162 hh0; hh0.x = h00; hh0.y = h01;
                __nv_bfloat162 hh1; hh1.x = h10; hh1.y = h11;
                *(__nv_bfloat162*)(oH + i0) = hh0;
                *(__nv_bfloat162*)(oH + i1) = hh1;
                __nv_bfloat162 ll0, ll1;
                ll0.x = __float2bfloat16(v00 - __bfloat162float(h00));
                ll0.y = __float2bfloat16(v01 - __bfloat162float(h01));
                ll1.x = __float2bfloat16(v10 - __bfloat162float(h10));
                ll1.y = __float2bfloat16(v11 - __bfloat162float(h11));
                *(__nv_bfloat162*)(oL + i0) = ll0;
                *(__nv_bfloat162*)(oL + i1) = ll1;
            }
        }
    }
}

// ---------------------------------------------------------------------------
// Launch
// ---------------------------------------------------------------------------
template <typename T>
static T* symaddr(const void* sym)
{
    void* p = nullptr;
    cudaGetSymbolAddress(&p, sym);
    return (T*)p;
}

extern "C" void kernel_launch(void* const* d_in, const int* in_sizes, int n_in,
                              void* d_out, int out_size)
{
    const float* x    = (const float*)d_in[0];
    const float* x_kv = (const float*)d_in[1];
    const float* Wq   = (const float*)d_in[2];
    const float* bq   = (const float*)d_in[3];
    const float* Wk   = (const float*)d_in[4];
    const float* bk   = (const float*)d_in[5];
    const float* Wv   = (const float*)d_in[6];
    const float* bv   = (const float*)d_in[7];
    const float* Wp   = (const float*)d_in[8];
    const float* bp   = (const float*)d_in[9];
    const float* g1   = (const float*)d_in[10];
    const float* b1   = (const float*)d_in[11];
    const float* g2   = (const float*)d_in[12];
    const float* b2   = (const float*)d_in[13];
    const float* W1   = (const float*)d_in[14];
    const float* bm1  = (const float*)d_in[15];
    const float* W2   = (const float*)d_in[16];
    const float* bm2  = (const float*)d_in[17];
    float* out = (float*)d_out;

    bf* h_hi  = symaddr<bf>(g_h_hi);   bf* h_lo  = symaddr<bf>(g_h_lo);
    bf* hk_hi = symaddr<bf>(g_hk_hi);  bf* hk_lo = symaddr<bf>(g_hk_lo);
    float* qb = symaddr<float>(g_q);
    float* kb = symaddr<float>(g_k);
    float* vb = symaddr<float>(g_v);
    bf* at_hi = symaddr<bf>(g_at_hi);  bf* at_lo = symaddr<bf>(g_at_lo);
    float* x2 = symaddr<float>(g_x2);
    bf* m_hi  = symaddr<bf>(g_m_hi);   bf* m_lo  = symaddr<bf>(g_m_lo);
    bf* t_hi  = symaddr<bf>(g_t_hi);   bf* t_lo  = symaddr<bf>(g_t_lo);
    bf* wq_hi = symaddr<bf>(g_wq_hi);  bf* wq_lo = symaddr<bf>(g_wq_lo);
    bf* wk_hi = symaddr<bf>(g_wk_hi);  bf* wk_lo = symaddr<bf>(g_wk_lo);
    bf* wv_hi = symaddr<bf>(g_wv_hi);  bf* wv_lo = symaddr<bf>(g_wv_lo);
    bf* wp_hi = symaddr<bf>(g_wp_hi);  bf* wp_lo = symaddr<bf>(g_wp_lo);
    bf* w1_hi = symaddr<bf>(g_w1_hi);  bf* w1_lo = symaddr<bf>(g_w1_lo);
    bf* w2_hi = symaddr<bf>(g_w2_hi);  bf* w2_lo = symaddr<bf>(g_w2_lo);

    static bool attrSet = false;
    if (!attrSet) {
        cudaFuncSetAttribute(mma_gemm<0>, cudaFuncAttributeMaxDynamicSharedMemorySize, SMTOT);
        cudaFuncSetAttribute(mma_gemm<1>, cudaFuncAttributeMaxDynamicSharedMemorySize, SMTOT);
        cudaFuncSetAttribute(mma_gemm<2>, cudaFuncAttributeMaxDynamicSharedMemorySize, SMTOT);
        attrSet = true;
    }

    // Weight transpose + split: one launch for all six weights
    convw_all<<<768, 256>>>(Wq, Wk, Wv, Wp, W1, W2,
                            wq_hi, wq_lo, wk_hi, wk_lo, wv_hi, wv_lo,
                            wp_hi, wp_lo, w1_hi, w1_lo, w2_hi, w2_lo);

    // LN1 on x and x_kv (-> bf16 hi/lo)
    {
        int blocks = ROWS / 8;
        ln_kernel<<<blocks, 256>>>(x,    g1, b1, h_hi,  h_lo,  ROWS);
        ln_kernel<<<blocks, 256>>>(x_kv, g1, b1, hk_hi, hk_lo, ROWS);
    }

    // QKV projections (fp32 out): grid 2x72 = 144 CTAs = one full wave
    {
        dim3 grid(Cc / 128, ROWS / 128);
        mma_gemm<0><<<grid, 256, SMTOT>>>(h_hi,  h_lo,  wq_hi, wq_lo, bq, nullptr, qb, nullptr, nullptr, ROWS, Cc, Cc);
        mma_gemm<0><<<grid, 256, SMTOT>>>(hk_hi, hk_lo, wk_hi, wk_lo, bk, nullptr, kb, nullptr, nullptr, ROWS, Cc, Cc);
        mma_gemm<0><<<grid, 256, SMTOT>>>(hk_hi, hk_lo, wv_hi, wv_lo, bv, nullptr, vb, nullptr, nullptr, ROWS, Cc, Cc);
    }

    // Sparse local attention (-> bf16 hi/lo)
    {
        int totalWarps = Bb * Nn * NH;  // 73728
        attn_kernel<<<totalWarps / 8, 256>>>(qb, kb, vb, at_hi, at_lo);
    }

    // x2 = x + att @ Wp + bp
    {
        dim3 grid(Cc / 128, ROWS / 128);
        mma_gemm<1><<<grid, 256, SMTOT>>>(at_hi, at_lo, wp_hi, wp_lo, bp, x, x2, nullptr, nullptr, ROWS, Cc, Cc);
    }

    // LN2 (-> bf16 hi/lo)
    ln_kernel<<<ROWS / 8, 256>>>(x2, g2, b2, m_hi, m_lo, ROWS);

    // MLP: t = gelu(m @ W1 + bm1) (-> bf16 hi/lo); out = x2 + t @ W2 + bm2
    {
        dim3 grid1(HID / 128, ROWS / 128);
        mma_gemm<2><<<grid1, 256, SMTOT>>>(m_hi, m_lo, w1_hi, w1_lo, bm1, nullptr, nullptr, t_hi, t_lo, ROWS, HID, Cc);
        dim3 grid2(Cc / 128, ROWS / 128);
        mma_gemm<1><<<grid2, 256, SMTOT>>>(t_hi, t_lo, w2_hi, w2_lo, bm2, x2, out, nullptr, nullptr, ROWS, Cc, HID);
    }
}